// round 12
// baseline (speedup 1.0000x reference)
#include <cuda_runtime.h>
#include <math.h>

#define N 512

typedef unsigned long long ull;

__device__ float2   g_ed[N * N];     // {d, e} per (row, col), full matrix
__device__ float    g_Ls[N];
__device__ int      g_perm[N];
__device__ double   g_partial[256];
__device__ unsigned g_cL, g_c1, g_c2, g_c3;   // zero-init; self-resetting

__device__ __forceinline__ int fbase(int i){
  return (i < 256) ? (i * 512) : ((i - 256) * 512 + 256);
}
__device__ __forceinline__ void fma2(ull &acc, ull a, ull b){
  asm("fma.rn.f32x2 %0, %1, %2, %0;" : "+l"(acc) : "l"(a), "l"(b));
}
__device__ __forceinline__ void add2(ull &acc, ull a){
  asm("add.rn.f32x2 %0, %0, %1;" : "+l"(acc) : "l"(a));
}
__device__ __forceinline__ float2 u2f(ull x){
  float2 f; asm("mov.b64 {%0,%1}, %2;" : "=f"(f.x), "=f"(f.y) : "l"(x)); return f;
}
__device__ __forceinline__ ull f2u(float a, float b){
  ull r; asm("mov.b64 %0, {%1,%2};" : "=l"(r) : "f"(a), "f"(b)); return r;
}
__device__ __forceinline__ float fsqrt_ap(float x){
  float r; asm("sqrt.approx.f32 %0, %1;" : "=f"(r) : "f"(x)); return r;
}
__device__ __forceinline__ float ex2_ap(float x){
  float r; asm("ex2.approx.f32 %0, %1;" : "=f"(r) : "f"(x)); return r;
}
__device__ __forceinline__ float lg2_ap(float x){
  float r; asm("lg2.approx.f32 %0, %1;" : "=f"(r) : "f"(x)); return r;
}

#define KE  (-0.72134752044448170f)   // -0.5 * log2(e)
#define LN2 ( 0.69314718055994531f)

__device__ __forceinline__ float2 make_de(float sq){
  const float d = fsqrt_ap(fmaxf(sq, 0.f));
  return make_float2(d, ex2_ap(KE * d));
}

struct GS {                       // phase-1 layout
  ulonglong2 Bv[64][17];          // B tile [kpair-pair][j]           17408 B
  ull        Au[32][128];         // A tile (off-diag uses rows 0-15) 32768 B
  float      Cp4[4][16][33];      // off-diag 4-way k-split partials   8448 B
  float      CpD[32][33];         // diag 2-way k-split partials       4224 B
  float      nrmA[32];
  float      nrmB[32];
};
struct LS {                       // phase-2 layout
  float2 ed0[N], ed1[N];          // staged {d,e} rows (natural col order)
  ull    pre[N], suf[N];          // packed {row0,row1} prefix/suffix sums
  ull    wf[16], wrv[16];
  double red[16];
};
union USm { GS g; LS l; };

__global__ void __launch_bounds__(512, 2) rnc_all(const float* __restrict__ feat,
                                                  const float* __restrict__ labels,
                                                  float* __restrict__ out)
{
  extern __shared__ char raw[];
  USm& S = *(USm*)raw;
  __shared__ float s_lab[256];
  __shared__ float s_Ls[N];
  __shared__ int   s_perm[N];
  __shared__ int   s_rankcnt;
  __shared__ bool  s_fin;

  const int t = threadIdx.x, lane = t & 31, w = t >> 5;
  const int b = blockIdx.x;

  // tile assignment: 240 half off-diagonal tiles (upper) + 16 diagonal tiles
  int bi, bj, half;
  if (b < 240){
    int p = b >> 1; half = b & 1;
    bi = 0;
    while (p >= 15 - bi){ p -= 15 - bi; bi++; }
    bj = bi + 1 + p;
  } else { bi = bj = b - 240; half = 0; }
  const int j0 = bj * 32;
  const int r0 = bi * 32 + ((b < 240) ? 16 * half : 0);
  const int nrows = (b < 240) ? 16 : 32;

  // ================= PHASE 1 =================================================
  if (t < 256) s_lab[t] = labels[t];
  if (t == 0)  s_rankcnt = 0;

  if (b < 240){                                      // A tile: 16 rows
#pragma unroll
    for (int p2 = 0; p2 < 2; p2++){
      const int idx = t + 512 * p2;
      const int row = idx >> 6, c = idx & 63;
      ((float4*)S.g.Au[row])[c] = *(const float4*)(feat + fbase(r0 + row) + 4 * c);
    }
  } else {                                           // A tile: 32 rows
#pragma unroll
    for (int p2 = 0; p2 < 4; p2++){
      const int idx = t + 512 * p2;
      const int row = idx >> 6, c = idx & 63;
      ((float4*)S.g.Au[row])[c] = *(const float4*)(feat + fbase(r0 + row) + 4 * c);
    }
  }
  {                                                  // B tile (32 js)
    const int j = t >> 4, u = t & 15;
#pragma unroll
    for (int p2 = 0; p2 < 4; p2++){
      const float4 v = *(const float4*)(feat + fbase(j0 + j) + 64 * p2 + 4 * u);
      S.g.Bv[16 * p2 + u][j] = make_ulonglong2(f2u(v.x, v.y), f2u(v.z, v.w));
    }
  }
  __syncthreads();

  // distributed label rank of label b (ballot + popc)
  if (t < 256){
    const float vb = s_lab[b];
    const float vt = s_lab[t];
    const bool pred = (vt < vb) || ((vt == vb) && (t < b));
    const unsigned bal = __ballot_sync(0xffffffffu, pred);
    if (lane == 0 && bal) atomicAdd(&s_rankcnt, __popc(bal));
  }
  __syncthreads();

  // early global sort write + signal (long before gram finishes)
  if (t == 0){
    const int r = s_rankcnt;
    const float vb = s_lab[b];
    g_Ls[2*r] = vb;   g_Ls[2*r + 1] = vb;
    g_perm[2*r] = b;  g_perm[2*r + 1] = b + 256;
    __threadfence();
    atomicAdd(&g_cL, 1u);
  }

  // norms
  if (t < nrows){
    ull a0 = 0, a1 = 0;
#pragma unroll 16
    for (int d2 = 0; d2 < 128; d2 += 2){
      fma2(a0, S.g.Au[t][d2],   S.g.Au[t][d2]);
      fma2(a1, S.g.Au[t][d2+1], S.g.Au[t][d2+1]);
    }
    const float2 f0 = u2f(a0), f1 = u2f(a1);
    S.g.nrmA[t] = (f0.x + f0.y) + (f1.x + f1.y);
  } else if (t >= 32 && t < 64){
    const int jn = t - 32;
    ull a0 = 0, a1 = 0;
#pragma unroll 16
    for (int q = 0; q < 64; q++){
      const ulonglong2 bv = S.g.Bv[q][jn];
      fma2(a0, bv.x, bv.x);
      fma2(a1, bv.y, bv.y);
    }
    const float2 f0 = u2f(a0), f1 = u2f(a1);
    S.g.nrmB[jn] = (f0.x + f0.y) + (f1.x + f1.y);
  }

  // main Gram loops
  float pd[4];
  const int w2 = w & 7, kh = w >> 3;
  if (b < 240){
    const int wr = w & 3, kq = w >> 2;      // 4 rows x k-quarter per warp
    ull acc[4] = {0, 0, 0, 0};
#pragma unroll
    for (int s = 0; s < 16; s++){
      const int q = kq * 16 + s;
      const ulonglong2 bv = S.g.Bv[q][lane];
#pragma unroll
      for (int rr = 0; rr < 4; rr++){
        const ulonglong2 av = *(const ulonglong2*)&S.g.Au[4*wr + rr][2*q];  // broadcast
        fma2(acc[rr], av.x, bv.x);
        fma2(acc[rr], av.y, bv.y);
      }
    }
#pragma unroll
    for (int rr = 0; rr < 4; rr++){
      const float2 g = u2f(acc[rr]);
      S.g.Cp4[kq][4*wr + rr][lane] = g.x + g.y;
    }
  } else {
    ull acc[4] = {0, 0, 0, 0};
#pragma unroll 8
    for (int s = 0; s < 32; s++){
      const int q = kh * 32 + s;
      const ulonglong2 bv = S.g.Bv[q][lane];
#pragma unroll
      for (int rr = 0; rr < 4; rr++){
        const ulonglong2 av = *(const ulonglong2*)&S.g.Au[4*w2 + rr][2*q];  // broadcast
        fma2(acc[rr], av.x, bv.x);
        fma2(acc[rr], av.y, bv.y);
      }
    }
#pragma unroll
    for (int rr = 0; rr < 4; rr++){ const float2 g = u2f(acc[rr]); pd[rr] = g.x + g.y; }
    if (kh == 1){
#pragma unroll
      for (int rr = 0; rr < 4; rr++) S.g.CpD[4*w2 + rr][lane] = pd[rr];
    }
  }
  __syncthreads();

  // epilogue: sq -> {d, e}; write both mirrors (scattered STGs absorbed)
  if (b < 240){
    const int row = t >> 5, col = t & 31;
    const float gsum = S.g.Cp4[0][row][col] + S.g.Cp4[1][row][col]
                     + S.g.Cp4[2][row][col] + S.g.Cp4[3][row][col];
    const float sq = S.g.nrmA[row] + S.g.nrmB[col] - 2.f * gsum;
    const float2 de = make_de(sq);
    const int gi = r0 + row, gj = j0 + col;
    g_ed[gi * N + gj] = de;
    g_ed[gj * N + gi] = de;
  } else if (kh == 0){
    const float nj = S.g.nrmB[lane];
#pragma unroll
    for (int rr = 0; rr < 4; rr++){
      const int gi = r0 + 4*w2 + rr, gj = j0 + lane;
      const float sq = S.g.nrmA[4*w2 + rr] + nj
                     - 2.f * (pd[rr] + S.g.CpD[4*w2 + rr][lane]);
      const float2 de = (gi == gj) ? make_float2(0.f, 1.f) : make_de(sq);
      g_ed[gi * N + gj] = de;
      g_ed[gj * N + gi] = de;
    }
  }

  // ---- pre-barrier: sorted labels ready long ago; load + searches here ------
  if (t == 0){
    while (*(volatile unsigned*)&g_cL < 256u) __nanosleep(32);
    __threadfence();
  }
  __syncthreads();
  s_Ls[t]   = __ldcg(&g_Ls[t]);
  s_perm[t] = __ldcg(&g_perm[t]);
  __syncthreads();

  const int   il = 2 * s_rankcnt;            // sorted position of label b's pair
  const float li = s_lab[b];
  const int   y  = t;
  const int   jj = s_perm[y];                // original row at this sorted pos
  const float lv = s_Ls[y];

  int a = 0, c = N;                          // label-interval boundaries for k=y
  if (y > il + 1){
    c = y & ~1;                              // pair start of lv (first occurrence)
    const float tk = lv - li;
    int lo = 0, len = il + 1;                // first m in [0, il] with |Ls-li| < tk
#pragma unroll 1
    for (int s = 0; s < 10; s++){
      if (len){ const int h = len >> 1, m = lo + h;
        if (!(fabsf(s_Ls[m] - li) < tk)){ lo = m + 1; len -= h + 1; } else len = h; }
    }
    a = lo;
  } else if (y < il){
    a = (y | 1) + 1;                         // one past lv's pair
    const float tk = li - lv;
    int lo = il, len = N - il;               // first m in [il, N) with |Ls-li| >= tk
#pragma unroll 1
    for (int s = 0; s < 10; s++){
      if (len){ const int h = len >> 1, m = lo + h;
        if (fabsf(s_Ls[m] - li) < tk){ lo = m + 1; len -= h + 1; } else len = h; }
    }
    c = lo;
  }

  // ================= GRID BARRIER (all 256 blocks co-resident) ================
  if (t == 0){
    __threadfence();
    atomicAdd(&g_c1, 1u);
    while (*(volatile unsigned*)&g_c1 < 256u) __nanosleep(64);
    __threadfence();
    if (atomicAdd(&g_c2, 1u) == 255u){ g_c1 = 0u; g_c2 = 0u; g_cL = 0u; __threadfence(); }
  }
  __syncthreads();     // also separates the smem union phases

  // ================= PHASE 2: loss for rows b and b+256 =======================
  // coalesced row loads (natural order), stage, then permute via smem
  S.l.ed0[t] = __ldcg(&g_ed[b * N + t]);
  S.l.ed1[t] = __ldcg(&g_ed[(b + 256) * N + t]);
  __syncthreads();
  const float2 de0 = S.l.ed0[jj];            // sorted order
  const float2 de1 = S.l.ed1[jj];
  const float d0 = de0.x, e0 = de0.y;
  const float d1 = de1.x, e1 = de1.y;

  // packed forward(prefix) + reverse(suffix) inclusive scans, rows {0,1} per ull
  ull pf = f2u(e0, e1), pr = pf;
#pragma unroll
  for (int o = 1; o < 32; o <<= 1){
    const ull vf = __shfl_up_sync  (0xffffffffu, pf, o);
    const ull vr = __shfl_down_sync(0xffffffffu, pr, o);
    if (lane >= o)      add2(pf, vf);
    if (lane + o < 32)  add2(pr, vr);
  }
  if (lane == 31) S.l.wf[w]  = pf;
  if (lane == 0)  S.l.wrv[w] = pr;
  __syncthreads();
  if (w == 0 && lane < 16){
    ull v = S.l.wf[lane];
#pragma unroll
    for (int o = 1; o < 16; o <<= 1){
      const ull u = __shfl_up_sync(0xffffu, v, o);
      if (lane >= o) add2(v, u);
    }
    S.l.wf[lane] = v;
  } else if (w == 1 && lane < 16){
    ull v = S.l.wrv[lane];
#pragma unroll
    for (int o = 1; o < 16; o <<= 1){
      const ull u = __shfl_down_sync(0xffffu, v, o);
      if (lane + o < 16) add2(v, u);
    }
    S.l.wrv[lane] = v;
  }
  __syncthreads();
  { ull v = pf; if (w > 0)  add2(v, S.l.wf[w - 1]);  S.l.pre[y] = v; }
  { ull v = pr; if (w < 15) add2(v, S.l.wrv[w + 1]); S.l.suf[y] = v; }
  __syncthreads();

  const float2 total = u2f(S.l.pre[N - 1]);

  float lg;
  if (y == il){                        // k = i0: row0 diag skip; row1 tk==0
    lg = lg2_ap(total.y - 1.f);
  } else if (y == il + 1){             // k = i1: row1 diag skip; row0 tk==0
    lg = lg2_ap(total.x - 1.f);
  } else {                             // neg = pre[a-1] + suf[c], no cancellation
    float2 PA = make_float2(0.f, 0.f), SC = make_float2(0.f, 0.f);
    if (a > 0) PA = u2f(S.l.pre[a - 1]);
    if (c < N) SC = u2f(S.l.suf[c]);
    lg = lg2_ap(PA.x + SC.x) + lg2_ap(PA.y + SC.y);
  }

  double acc2 = 0.5 * (double)(d0 + d1) + (double)LN2 * (double)lg;

#pragma unroll
  for (int o = 16; o; o >>= 1) acc2 += __shfl_xor_sync(0xffffffffu, acc2, o);
  if (lane == 0) S.l.red[w] = acc2;
  __syncthreads();

  if (w == 0){
    double v = (lane < 16) ? S.l.red[lane] : 0.0;
#pragma unroll
    for (int o = 8; o; o >>= 1) v += __shfl_xor_sync(0xffffffffu, v, o);
    if (lane == 0){
      g_partial[b] = v;
      __threadfence();
      s_fin = (atomicAdd(&g_c3, 1u) == 255u);
    }
  }
  __syncthreads();

  if (s_fin){
    double v = (t < 256) ? *((volatile double*)&g_partial[t]) : 0.0;
#pragma unroll
    for (int o = 16; o; o >>= 1) v += __shfl_xor_sync(0xffffffffu, v, o);
    if (lane == 0) S.l.red[w] = v;
    __syncthreads();
    if (w == 0){
      double s = (lane < 16) ? S.l.red[lane] : 0.0;
#pragma unroll
      for (int o = 8; o; o >>= 1) s += __shfl_xor_sync(0xffffffffu, s, o);
      if (lane == 0){
        out[0] = (float)(s / (512.0 * 511.0));
        g_c3 = 0;
      }
    }
  }
}

extern "C" void kernel_launch(void* const* d_in, const int* in_sizes, int n_in,
                              void* d_out, int out_size)
{
  const float* feat   = (const float*)d_in[0];
  const float* labels = (const float*)d_in[1];
  float* out = (float*)d_out;

  cudaFuncSetAttribute(rnc_all, cudaFuncAttributeMaxDynamicSharedMemorySize,
                       (int)sizeof(USm));
  rnc_all<<<256, 512, sizeof(USm)>>>(feat, labels, out);
}

// round 13
// speedup vs baseline: 1.1807x; 1.1807x over previous
#include <cuda_runtime.h>
#include <math.h>

#define N  512
#define NB 272     // 136 upper-triangle (incl. diagonal) 32x32 tiles x 2 halves

typedef unsigned long long ull;

__device__ float    g_sq[N * N];
__device__ float    g_Ls[N];
__device__ int      g_perm[N];
__device__ double   g_partial[256];
__device__ unsigned g_c1, g_c2, g_c3;   // zero-init; self-resetting

__device__ __forceinline__ int fbase(int i){
  return (i < 256) ? (i * 512) : ((i - 256) * 512 + 256);
}
__device__ __forceinline__ void fma2(ull &acc, ull a, ull b){
  asm("fma.rn.f32x2 %0, %1, %2, %0;" : "+l"(acc) : "l"(a), "l"(b));
}
__device__ __forceinline__ void add2(ull &acc, ull a){
  asm("add.rn.f32x2 %0, %0, %1;" : "+l"(acc) : "l"(a));
}
__device__ __forceinline__ float2 u2f(ull x){
  float2 f; asm("mov.b64 {%0,%1}, %2;" : "=f"(f.x), "=f"(f.y) : "l"(x)); return f;
}
__device__ __forceinline__ ull f2u(float a, float b){
  ull r; asm("mov.b64 %0, {%1,%2};" : "=l"(r) : "f"(a), "f"(b)); return r;
}
__device__ __forceinline__ float fsqrt_ap(float x){
  float r; asm("sqrt.approx.f32 %0, %1;" : "=f"(r) : "f"(x)); return r;
}
__device__ __forceinline__ float ex2_ap(float x){
  float r; asm("ex2.approx.f32 %0, %1;" : "=f"(r) : "f"(x)); return r;
}
__device__ __forceinline__ float lg2_ap(float x){
  float r; asm("lg2.approx.f32 %0, %1;" : "=f"(r) : "f"(x)); return r;
}

struct GS {                       // phase-1 layout (uniform: 16 rows x 32 cols)
  ulonglong2 Bv[64][17];          // B tile [kpair-pair][j]          17408 B
  ull        Au[16][128];         // A tile [row][k-pair]            16384 B
  float      Cp4[4][16][33];      // 4-way k-split partials           8448 B
  float      nrmA[16];
  float      nrmB[32];
};
struct LS {                       // phase-2 layout (round-10 proven)
  float  Ls[N];  int perm[N];
  float  sq0[N], sq1[N];
  ull    pre[N], suf[N];          // packed {row0,row1} prefix/suffix sums
  ull    wf[16], wrv[16];
  double red[16];
};
union USm { GS g; LS l; };

__global__ void __launch_bounds__(512, 2) rnc_all(const float* __restrict__ feat,
                                                  const float* __restrict__ labels,
                                                  float* __restrict__ out)
{
  extern __shared__ char raw[];
  USm& S = *(USm*)raw;
  __shared__ float s_lab[256];
  __shared__ int   s_rankcnt;
  __shared__ bool  s_fin;

  const int t = threadIdx.x, lane = t & 31, w = t >> 5;
  const int b = blockIdx.x;

  // tile decode: p = tile index among 136 upper-incl-diagonal tiles
  int p = b >> 1;
  const int half = b & 1;
  int bi = 0;
  while (p >= 16 - bi){ p -= 16 - bi; bi++; }
  const int bj = bi + p;
  const int j0 = bj * 32;
  const int r0 = bi * 32 + 16 * half;

  // ================= PHASE 1: one 16x32 Gram half-tile per block ==============
  if (t < 256) s_lab[t] = labels[t];
  if (t == 0)  s_rankcnt = 0;

  // A tile [16 rows][256 k] natural layout (k-pairs in ull halves)
#pragma unroll
  for (int p2 = 0; p2 < 2; p2++){
    const int idx = t + 512 * p2;                 // 0..1023
    const int row = idx >> 6, c = idx & 63;
    ((float4*)S.g.Au[row])[c] = *(const float4*)(feat + fbase(r0 + row) + 4 * c);
  }
  // B tile (32 js), kpair-pair layout
  {
    const int j = t >> 4, u = t & 15;
#pragma unroll
    for (int p2 = 0; p2 < 4; p2++){
      const float4 v = *(const float4*)(feat + fbase(j0 + j) + 64 * p2 + 4 * u);
      S.g.Bv[16 * p2 + u][j] = make_ulonglong2(f2u(v.x, v.y), f2u(v.z, v.w));
    }
  }
  __syncthreads();

  // distributed label rank of label b (only blocks < 256 own a label)
  if (b < 256 && t < 256){
    const float vb = s_lab[b];
    const float vt = s_lab[t];
    const bool pred = (vt < vb) || ((vt == vb) && (t < b));
    const unsigned bal = __ballot_sync(0xffffffffu, pred);
    if (lane == 0 && bal) atomicAdd(&s_rankcnt, __popc(bal));
  }

  // norms: t<16 rows, t in [32,64) js
  if (t < 16){
    ull a0 = 0, a1 = 0;
#pragma unroll 16
    for (int d2 = 0; d2 < 128; d2 += 2){
      fma2(a0, S.g.Au[t][d2],   S.g.Au[t][d2]);
      fma2(a1, S.g.Au[t][d2+1], S.g.Au[t][d2+1]);
    }
    const float2 f0 = u2f(a0), f1 = u2f(a1);
    S.g.nrmA[t] = (f0.x + f0.y) + (f1.x + f1.y);
  } else if (t >= 32 && t < 64){
    const int jn = t - 32;
    ull a0 = 0, a1 = 0;
#pragma unroll 16
    for (int q = 0; q < 64; q++){
      const ulonglong2 bv = S.g.Bv[q][jn];
      fma2(a0, bv.x, bv.x);
      fma2(a1, bv.y, bv.y);
    }
    const float2 f0 = u2f(a0), f1 = u2f(a1);
    S.g.nrmB[jn] = (f0.x + f0.y) + (f1.x + f1.y);
  }

  // main Gram loop: warp -> 4 rows x k-quarter; lane -> j
  {
    const int wr = w & 3, kq = w >> 2;
    ull acc[4] = {0, 0, 0, 0};
#pragma unroll
    for (int s = 0; s < 16; s++){
      const int q = kq * 16 + s;
      const ulonglong2 bv = S.g.Bv[q][lane];      // LDS.128
#pragma unroll
      for (int rr = 0; rr < 4; rr++){
        const ulonglong2 av = *(const ulonglong2*)&S.g.Au[4*wr + rr][2*q];  // broadcast
        fma2(acc[rr], av.x, bv.x);
        fma2(acc[rr], av.y, bv.y);
      }
    }
#pragma unroll
    for (int rr = 0; rr < 4; rr++){
      const float2 g = u2f(acc[rr]);
      S.g.Cp4[kq][4*wr + rr][lane] = g.x + g.y;
    }
  }
  __syncthreads();

  // sort write (pre-barrier; visible after grid barrier)
  if (b < 256 && t == 0){
    const int r = s_rankcnt;
    const float vb = s_lab[b];
    g_Ls[2*r] = vb;   g_Ls[2*r + 1] = vb;
    g_perm[2*r] = b;  g_perm[2*r + 1] = b + 256;
  }

  // epilogue: sq = ni + nj - 2g ; write cell + mirror
  {
    const int row = t >> 5, col = t & 31;         // 16 x 32 outputs, 1 per thread
    const float gsum = S.g.Cp4[0][row][col] + S.g.Cp4[1][row][col]
                     + S.g.Cp4[2][row][col] + S.g.Cp4[3][row][col];
    const float sq = S.g.nrmA[row] + S.g.nrmB[col] - 2.f * gsum;
    const int gi = r0 + row, gj = j0 + col;
    g_sq[gi * N + gj] = sq;
    g_sq[gj * N + gi] = sq;                       // diag tiles: duplicate, identical
  }
  __syncthreads();

  // ================= GRID BARRIER (272 blocks, all co-resident) ===============
  if (t == 0){
    __threadfence();
    atomicAdd(&g_c1, 1u);
  }
  if (b >= 256) return;                           // helpers done (arrived already)
  if (t == 0){
    while (*(volatile unsigned*)&g_c1 < (unsigned)NB) __nanosleep(64);
    __threadfence();
    if (atomicAdd(&g_c2, 1u) == 255u){ g_c1 = 0u; g_c2 = 0u; __threadfence(); }
  }
  __syncthreads();     // also separates the smem union phases

  // ================= PHASE 2: loss for rows b and b+256 (round-10 path) =======
  S.l.Ls[t]   = __ldcg(&g_Ls[t]);
  S.l.perm[t] = __ldcg(&g_perm[t]);
  S.l.sq0[t]  = __ldcg(&g_sq[b * N + t]);
  S.l.sq1[t]  = __ldcg(&g_sq[(b + 256) * N + t]);
  __syncthreads();

  const int   il  = 2 * s_rankcnt;           // sorted position of label b's pair
  const float li  = s_lab[b];
  const float KE  = -0.72134752044448170f;   // -0.5 * log2(e)
  const float LN2 =  0.69314718055994531f;

  const int y = t;                 // sorted position handled by this thread
  const int j = S.l.perm[y];
  const float d0 = (y == il    ) ? 0.f : fsqrt_ap(fmaxf(S.l.sq0[j], 0.f));
  const float d1 = (y == il + 1) ? 0.f : fsqrt_ap(fmaxf(S.l.sq1[j], 0.f));
  const float e0 = (y == il    ) ? 1.f : ex2_ap(KE * d0);
  const float e1 = (y == il + 1) ? 1.f : ex2_ap(KE * d1);

  // packed forward(prefix) + reverse(suffix) inclusive scans, rows {0,1} per ull
  ull pf = f2u(e0, e1), pr = pf;
#pragma unroll
  for (int o = 1; o < 32; o <<= 1){
    const ull vf = __shfl_up_sync  (0xffffffffu, pf, o);
    const ull vr = __shfl_down_sync(0xffffffffu, pr, o);
    if (lane >= o)      add2(pf, vf);
    if (lane + o < 32)  add2(pr, vr);
  }
  if (lane == 31) S.l.wf[w]  = pf;
  if (lane == 0)  S.l.wrv[w] = pr;
  __syncthreads();
  if (w == 0 && lane < 16){
    ull v = S.l.wf[lane];
#pragma unroll
    for (int o = 1; o < 16; o <<= 1){
      const ull u = __shfl_up_sync(0xffffu, v, o);
      if (lane >= o) add2(v, u);
    }
    S.l.wf[lane] = v;
  } else if (w == 1 && lane < 16){
    ull v = S.l.wrv[lane];
#pragma unroll
    for (int o = 1; o < 16; o <<= 1){
      const ull u = __shfl_down_sync(0xffffu, v, o);
      if (lane + o < 16) add2(v, u);
    }
    S.l.wrv[lane] = v;
  }
  __syncthreads();
  { ull v = pf; if (w > 0)  add2(v, S.l.wf[w - 1]);  S.l.pre[y] = v; }
  { ull v = pr; if (w < 15) add2(v, S.l.wrv[w + 1]); S.l.suf[y] = v; }
  __syncthreads();

  const float2 total = u2f(S.l.pre[N - 1]);
  const float  lv = S.l.Ls[y];

  float lg;
  if (y == il){                        // k = i0: row0 diag skip; row1 tk==0
    lg = lg2_ap(total.y - 1.f);
  } else if (y == il + 1){             // k = i1: row1 diag skip; row0 tk==0
    lg = lg2_ap(total.x - 1.f);
  } else {
    int a, c;
    if (y > il){                       // lv > li: right boundary free (pair start)
      c = y & ~1;
      const float tk = lv - li;
      int lo = 0, len = il + 1;        // first m in [0, il] with |Ls-li| < tk
#pragma unroll 1
      for (int s = 0; s < 10; s++){
        if (len){ const int h = len >> 1, m = lo + h;
          if (!(fabsf(S.l.Ls[m] - li) < tk)){ lo = m + 1; len -= h + 1; } else len = h; }
      }
      a = lo;
    } else {                           // lv < li: left boundary free (past pair)
      a = (y | 1) + 1;
      const float tk = li - lv;
      int lo = il, len = N - il;       // first m in [il, N) with |Ls-li| >= tk
#pragma unroll 1
      for (int s = 0; s < 10; s++){
        if (len){ const int h = len >> 1, m = lo + h;
          if (fabsf(S.l.Ls[m] - li) < tk){ lo = m + 1; len -= h + 1; } else len = h; }
      }
      c = lo;
    }
    float2 PA = make_float2(0.f, 0.f), SC = make_float2(0.f, 0.f);
    if (a > 0) PA = u2f(S.l.pre[a - 1]);
    if (c < N) SC = u2f(S.l.suf[c]);
    lg = lg2_ap(PA.x + SC.x) + lg2_ap(PA.y + SC.y);   // neg = pre + suf
  }

  double acc2 = 0.5 * (double)(d0 + d1) + (double)LN2 * (double)lg;

#pragma unroll
  for (int o = 16; o; o >>= 1) acc2 += __shfl_xor_sync(0xffffffffu, acc2, o);
  if (lane == 0) S.l.red[w] = acc2;
  __syncthreads();

  if (w == 0){
    double v = (lane < 16) ? S.l.red[lane] : 0.0;
#pragma unroll
    for (int o = 8; o; o >>= 1) v += __shfl_xor_sync(0xffffffffu, v, o);
    if (lane == 0){
      g_partial[b] = v;
      __threadfence();
      s_fin = (atomicAdd(&g_c3, 1u) == 255u);
    }
  }
  __syncthreads();

  if (s_fin){
    double v = (t < 256) ? *((volatile double*)&g_partial[t]) : 0.0;
#pragma unroll
    for (int o = 16; o; o >>= 1) v += __shfl_xor_sync(0xffffffffu, v, o);
    if (lane == 0) S.l.red[w] = v;
    __syncthreads();
    if (w == 0){
      double s = (lane < 16) ? S.l.red[lane] : 0.0;
#pragma unroll
      for (int o = 8; o; o >>= 1) s += __shfl_xor_sync(0xffffffffu, s, o);
      if (lane == 0){
        out[0] = (float)(s / (512.0 * 511.0));
        g_c3 = 0;
      }
    }
  }
}

extern "C" void kernel_launch(void* const* d_in, const int* in_sizes, int n_in,
                              void* d_out, int out_size)
{
  const float* feat   = (const float*)d_in[0];
  const float* labels = (const float*)d_in[1];
  float* out = (float*)d_out;

  cudaFuncSetAttribute(rnc_all, cudaFuncAttributeMaxDynamicSharedMemorySize,
                       (int)sizeof(USm));
  rnc_all<<<NB, 512, sizeof(USm)>>>(feat, labels, out);
}